// round 5
// baseline (speedup 1.0000x reference)
#include <cuda_runtime.h>
#include <math.h>
#include <stdint.h>

// ---------------------------------------------------------------------------
// Quantizer: x [4,16,1024] f32, codebook [65536,16] f32.
// out[0:65536] = nearest codebook entry per token, [B,D,T]; out[65536] = loss.
//
// Pass 1: int8 dp4a computes approx scores (exact int arithmetic on quantized
// operands, rigorous error bound E). Keeps per-(token, 64-code tile) max only.
// Pass 2: exact fp32 rescore of tiles within 2E of the max -> exact argmin
// (same selection code that passed R1/R2/R4 with rel_err 9.4e-8).
// ---------------------------------------------------------------------------

#define TOKENS   4096
#define NCODES   65536
#define DIM      16
#define STC      64                  // codes per tile
#define NST      (NCODES / STC)      // 1024
#define NGR      36                  // code groups (grid.y)
#define NINF     __int_as_float(0xff800000)

__device__ unsigned g_scal[4];           // maxX, maxC, SAc (float bits)
__device__ int4     g_Bq[NCODES];        // packed int8 codes, 1 MB
__device__ int      g_bias[NCODES];      // bias in int score units
__device__ float    g_tb[(size_t)NST * TOKENS];  // 16 MB tile maxima (scaled)
__device__ float    g_err[TOKENS];

__device__ __forceinline__ void cpasync16(const void* dst_smem, const void* src) {
    unsigned s = (unsigned)__cvta_generic_to_shared(dst_smem);
    asm volatile("cp.async.cg.shared.global [%0], [%1], 16;" :: "r"(s), "l"(src));
}
#define CP_COMMIT() asm volatile("cp.async.commit_group;")
#define CP_WAIT(n)  asm volatile("cp.async.wait_group %0;" :: "n"(n))

__device__ __forceinline__ int pack4(int a0, int a1, int a2, int a3) {
    return (a0 & 0xFF) | ((a1 & 0xFF) << 8) | ((a2 & 0xFF) << 16) | (a3 << 24);
}

// ---------------------------------------------------------------------------
// Phase -1: zero the atomic-max scalars (graph replays must be deterministic).
// ---------------------------------------------------------------------------
__global__ void init_kernel() {
    if (threadIdx.x < 4) g_scal[threadIdx.x] = 0u;
}

// ---------------------------------------------------------------------------
// Phase 0a: maxima reductions (deterministic: bitwise atomicMax of positive
// float patterns is order-independent).
// ---------------------------------------------------------------------------
__global__ __launch_bounds__(256) void prepA_kernel(const float* __restrict__ x,
                                                    const float* __restrict__ cb) {
    __shared__ float sm[3][256];
    int i = blockIdx.x * 256 + threadIdx.x;          // 0..65535
    float ax = fabsf(x[i]);                          // x has exactly 65536 elems
    const float* c = cb + (size_t)i * DIM;
    float mc = 0.0f, sa = 0.0f;
#pragma unroll
    for (int d = 0; d < DIM; d++) { float a = fabsf(c[d]); mc = fmaxf(mc, a); sa += a; }
    sm[0][threadIdx.x] = ax; sm[1][threadIdx.x] = mc; sm[2][threadIdx.x] = sa;
    __syncthreads();
    for (int s = 128; s > 0; s >>= 1) {
        if (threadIdx.x < s) {
#pragma unroll
            for (int k = 0; k < 3; k++)
                sm[k][threadIdx.x] = fmaxf(sm[k][threadIdx.x], sm[k][threadIdx.x + s]);
        }
        __syncthreads();
    }
    if (threadIdx.x == 0) {
#pragma unroll
        for (int k = 0; k < 3; k++)
            atomicMax(&g_scal[k], __float_as_uint(sm[k][0]));
    }
}

// ---------------------------------------------------------------------------
// Phase 0b: quantize codebook to int8 + int bias.
// ---------------------------------------------------------------------------
__global__ __launch_bounds__(256) void prepB_kernel(const float* __restrict__ cb) {
    int i = blockIdx.x * 256 + threadIdx.x;
    const float maxX = __uint_as_float(g_scal[0]);
    const float maxC = __uint_as_float(g_scal[1]);
    const float sx = maxX * (1.0f / 127.0f);
    const float sc = maxC * (1.0f / 127.0f);
    const float qc = 127.0f / maxC;
    const float* c = cb + (size_t)i * DIM;
    int q[DIM];
    float h = 0.0f;
#pragma unroll
    for (int d = 0; d < DIM; d++) {
        float v = c[d];
        h = fmaf(v, v, h);
        q[d] = __float2int_rn(v * qc);               // in [-127,127], no clip
    }
    int4 w;
    w.x = pack4(q[0], q[1], q[2], q[3]);
    w.y = pack4(q[4], q[5], q[6], q[7]);
    w.z = pack4(q[8], q[9], q[10], q[11]);
    w.w = pack4(q[12], q[13], q[14], q[15]);
    g_Bq[i] = w;
    g_bias[i] = __float2int_rn(-0.5f * h / (sx * sc));
}

// ---------------------------------------------------------------------------
// Phase 1: int8 dp4a scan. grid (8, 36), 256 threads, 2 tokens/thread.
// Per tile: running int max per token; store scaled float tile max.
// ---------------------------------------------------------------------------
__global__ __launch_bounds__(256, 2) void scan_kernel(const float* __restrict__ x) {
    __shared__ int4 sQ[2][STC];     // 2 x 1 KB
    __shared__ int  sB[2][STC];     // 2 x 256 B

    const int tid = threadIdx.x;
    const int tok0 = blockIdx.x * 512 + tid;   // grid.x = 8
    const int tok1 = tok0 + 256;               // same 1024-token batch
    const int b = tok0 >> 10;
    const int grp = blockIdx.y;                // grid.y = 36
    const int st0 = (grp * NST) / NGR;
    const int st1 = ((grp + 1) * NST) / NGR;

    const float maxX = __uint_as_float(g_scal[0]);
    const float maxC = __uint_as_float(g_scal[1]);
    const float sx = maxX * (1.0f / 127.0f);
    const float sc = maxC * (1.0f / 127.0f);
    const float s  = sx * sc;
    const float qx = 127.0f / maxX;

    // quantize this thread's two tokens into packed int8 registers
    const float* xp = x + (size_t)b * (DIM * 1024);
    int xq0[4], xq1[4];
#pragma unroll
    for (int w = 0; w < 4; w++) {
        int q0[4], q1[4];
#pragma unroll
        for (int j = 0; j < 4; j++) {
            int d = w * 4 + j;
            q0[j] = __float2int_rn(xp[d * 1024 + (tok0 & 1023)] * qx);
            q1[j] = __float2int_rn(xp[d * 1024 + (tok1 & 1023)] * qx);
        }
        xq0[w] = pack4(q0[0], q0[1], q0[2], q0[3]);
        xq1[w] = pack4(q1[0], q1[1], q1[2], q1[3]);
    }

    // prefetch first tile
    if (tid < STC)
        cpasync16(&sQ[0][tid], &g_Bq[st0 * STC + tid]);
    else if (tid < STC + 16)
        cpasync16(&sB[0][(tid - STC) * 4], &g_bias[st0 * STC + (tid - STC) * 4]);
    CP_COMMIT();

    for (int st = st0; st < st1; st++) {
        const int buf = (st - st0) & 1;
        if (st + 1 < st1) {
            if (tid < STC)
                cpasync16(&sQ[buf ^ 1][tid], &g_Bq[(st + 1) * STC + tid]);
            else if (tid < STC + 16)
                cpasync16(&sB[buf ^ 1][(tid - STC) * 4],
                          &g_bias[(st + 1) * STC + (tid - STC) * 4]);
            CP_COMMIT();
            CP_WAIT(1);
        } else {
            CP_WAIT(0);
        }
        __syncthreads();

        int m0 = INT_MIN, m1 = INT_MIN;
        const int4* q4 = sQ[buf];
        const int4* b4 = (const int4*)sB[buf];
#pragma unroll 4
        for (int g = 0; g < STC / 4; g++) {
            int4 bb = b4[g];
            int bias[4] = {bb.x, bb.y, bb.z, bb.w};
#pragma unroll
            for (int u = 0; u < 4; u++) {
                int4 q = q4[g * 4 + u];
                int a0 = __dp4a(q.x, xq0[0], bias[u]);
                a0 = __dp4a(q.y, xq0[1], a0);
                a0 = __dp4a(q.z, xq0[2], a0);
                a0 = __dp4a(q.w, xq0[3], a0);
                int a1 = __dp4a(q.x, xq1[0], bias[u]);
                a1 = __dp4a(q.y, xq1[1], a1);
                a1 = __dp4a(q.z, xq1[2], a1);
                a1 = __dp4a(q.w, xq1[3], a1);
                m0 = max(m0, a0);
                m1 = max(m1, a1);
            }
        }
        g_tb[(size_t)st * TOKENS + tok0] = (float)m0 * s;
        g_tb[(size_t)st * TOKENS + tok1] = (float)m1 * s;
        __syncthreads();
    }
}

// ---------------------------------------------------------------------------
// Phase 2: exact fp32 rescore of candidate tiles + gather + per-token error.
// ---------------------------------------------------------------------------
__global__ __launch_bounds__(256) void finish_kernel(const float* __restrict__ x,
                                                     const float* __restrict__ cb,
                                                     float* __restrict__ out) {
    int token = blockIdx.x * 256 + threadIdx.x;
    int bb = token >> 10, t = token & 1023;

    float xr[DIM], SAx = 0.0f;
#pragma unroll
    for (int d = 0; d < DIM; d++) {
        xr[d] = x[(size_t)bb * (DIM * 1024) + d * 1024 + t];
        SAx += fabsf(xr[d]);
    }

    const float maxX = __uint_as_float(g_scal[0]);
    const float maxC = __uint_as_float(g_scal[1]);
    const float SAc  = __uint_as_float(g_scal[2]);
    const float sx = maxX * (1.0f / 127.0f);
    const float sc = maxC * (1.0f / 127.0f);
    // rigorous per-score error bound (quantization + bias rounding + fp slack)
    const float E = 0.5f * sc * SAx + 0.5f * sx * SAc
                  + 16.0f * sx * sc + sx * sc + 1e-2f;

    float m = NINF;
#pragma unroll 8
    for (int ti = 0; ti < NST; ti++)
        m = fmaxf(m, g_tb[(size_t)ti * TOKENS + token]);
    const float thr = m - 2.0f * E;

    float best = NINF;
    int   bi   = 0;
    for (int ti = 0; ti < NST; ti++) {
        if (g_tb[(size_t)ti * TOKENS + token] < thr) continue;
        const int c0 = ti * STC;
        for (int c = c0; c < c0 + STC; c++) {
            const float* cr = cb + (size_t)c * DIM;
            float acc = 0.0f, h = 0.0f;
#pragma unroll
            for (int d = 0; d < DIM; d++) {
                float v = cr[d];
                acc = fmaf(v, xr[d], acc);
                h   = fmaf(v, v, h);
            }
            float sscore = acc - 0.5f * h;
            if (sscore > best) { best = sscore; bi = c; }  // strict >: first idx
        }
    }

    const float* q = cb + (size_t)bi * DIM;
    float err = 0.0f;
#pragma unroll
    for (int d = 0; d < DIM; d++) {
        float qd = q[d];
        float df = qd - xr[d];
        err = fmaf(df, df, err);
        out[(size_t)bb * (DIM * 1024) + d * 1024 + t] = qd;
    }
    g_err[token] = err;
}

// ---------------------------------------------------------------------------
// Phase 3: deterministic loss reduction.
// ---------------------------------------------------------------------------
__global__ __launch_bounds__(1024) void loss_kernel(float* __restrict__ out,
                                                    int out_size) {
    __shared__ float sh[1024];
    int tid = threadIdx.x;
    float v = 0.0f;
#pragma unroll
    for (int i = 0; i < TOKENS / 1024; i++)
        v += g_err[tid * (TOKENS / 1024) + i];
    sh[tid] = v;
    __syncthreads();
    for (int stride = 512; stride > 0; stride >>= 1) {
        if (tid < stride) sh[tid] += sh[tid + stride];
        __syncthreads();
    }
    if (tid == 0 && out_size > NCODES)
        out[NCODES] = sh[0] / (float)(TOKENS * DIM);
}

// ---------------------------------------------------------------------------
extern "C" void kernel_launch(void* const* d_in, const int* in_sizes, int n_in,
                              void* d_out, int out_size) {
    const float* x  = (const float*)d_in[0];   // [4,16,1024]
    const float* cb = (const float*)d_in[1];   // [65536,16]
    float* out = (float*)d_out;

    init_kernel<<<1, 32>>>();
    prepA_kernel<<<NCODES / 256, 256>>>(x, cb);
    prepB_kernel<<<NCODES / 256, 256>>>(cb);

    dim3 grid(TOKENS / 512, NGR);
    scan_kernel<<<grid, 256>>>(x);

    finish_kernel<<<TOKENS / 256, 256>>>(x, cb, out);

    loss_kernel<<<1, 1024>>>(out, out_size);
}

// round 6
// speedup vs baseline: 35.9990x; 35.9990x over previous
#include <cuda_runtime.h>
#include <math.h>
#include <stdint.h>

// ---------------------------------------------------------------------------
// Quantizer: x [4,16,1024] f32, codebook [65536,16] f32.
// out[0:65536] = nearest codebook entry per token, [B,D,T]; out[65536] = loss.
//
// Pass 1: int8 dp4a scores (exact int arithmetic, rigorous error bound E),
// per-(token, 64-code tile) max only. Pass 2 (warp-per-token): exact fp32
// rescore of tiles within 2E of the max -> exact argmin.
// ---------------------------------------------------------------------------

#define TOKENS   4096
#define NCODES   65536
#define DIM      16
#define STC      64                  // codes per tile
#define NST      (NCODES / STC)      // 1024
#define NGR      36                  // code groups (grid.y) in scan
#define NINF     __int_as_float(0xff800000)

__device__ unsigned g_scal[4];           // maxX, maxC, SAc (float bits)
__device__ int4     g_Bq[NCODES];        // packed int8 codes, 1 MB
__device__ int      g_bias[NCODES];      // bias in int score units
__device__ float    g_tb[(size_t)NST * TOKENS];  // tile maxima (scaled), 16 MB
__device__ float    g_err[TOKENS];

__device__ __forceinline__ void cpasync16(const void* dst_smem, const void* src) {
    unsigned s = (unsigned)__cvta_generic_to_shared(dst_smem);
    asm volatile("cp.async.cg.shared.global [%0], [%1], 16;" :: "r"(s), "l"(src));
}
#define CP_COMMIT() asm volatile("cp.async.commit_group;")
#define CP_WAIT(n)  asm volatile("cp.async.wait_group %0;" :: "n"(n))

__device__ __forceinline__ int pack4(int a0, int a1, int a2, int a3) {
    return (a0 & 0xFF) | ((a1 & 0xFF) << 8) | ((a2 & 0xFF) << 16) | (a3 << 24);
}

// ---------------------------------------------------------------------------
__global__ void init_kernel() {
    if (threadIdx.x < 4) g_scal[threadIdx.x] = 0u;
}

// Phase 0a: maxima reductions (deterministic: bitwise atomicMax on positive
// float patterns is order-independent).
__global__ __launch_bounds__(256) void prepA_kernel(const float* __restrict__ x,
                                                    const float* __restrict__ cb) {
    __shared__ float sm[3][256];
    int i = blockIdx.x * 256 + threadIdx.x;          // 0..65535
    float ax = fabsf(x[i]);                          // x has exactly 65536 elems
    const float* c = cb + (size_t)i * DIM;
    float mc = 0.0f, sa = 0.0f;
#pragma unroll
    for (int d = 0; d < DIM; d++) { float a = fabsf(c[d]); mc = fmaxf(mc, a); sa += a; }
    sm[0][threadIdx.x] = ax; sm[1][threadIdx.x] = mc; sm[2][threadIdx.x] = sa;
    __syncthreads();
    for (int s = 128; s > 0; s >>= 1) {
        if (threadIdx.x < s) {
#pragma unroll
            for (int k = 0; k < 3; k++)
                sm[k][threadIdx.x] = fmaxf(sm[k][threadIdx.x], sm[k][threadIdx.x + s]);
        }
        __syncthreads();
    }
    if (threadIdx.x == 0) {
#pragma unroll
        for (int k = 0; k < 3; k++)
            atomicMax(&g_scal[k], __float_as_uint(sm[k][0]));
    }
}

// Phase 0b: quantize codebook to int8 + int bias.
__global__ __launch_bounds__(256) void prepB_kernel(const float* __restrict__ cb) {
    int i = blockIdx.x * 256 + threadIdx.x;
    const float maxX = __uint_as_float(g_scal[0]);
    const float maxC = __uint_as_float(g_scal[1]);
    const float sx = maxX * (1.0f / 127.0f);
    const float sc = maxC * (1.0f / 127.0f);
    const float qc = 127.0f / maxC;
    const float* c = cb + (size_t)i * DIM;
    int q[DIM];
    float h = 0.0f;
#pragma unroll
    for (int d = 0; d < DIM; d++) {
        float v = c[d];
        h = fmaf(v, v, h);
        q[d] = __float2int_rn(v * qc);               // in [-127,127], no clip
    }
    int4 w;
    w.x = pack4(q[0], q[1], q[2], q[3]);
    w.y = pack4(q[4], q[5], q[6], q[7]);
    w.z = pack4(q[8], q[9], q[10], q[11]);
    w.w = pack4(q[12], q[13], q[14], q[15]);
    g_Bq[i] = w;
    g_bias[i] = __float2int_rn(-0.5f * h / (sx * sc));
}

// ---------------------------------------------------------------------------
// Phase 1: int8 dp4a scan (unchanged from R5; measured 80us).
// grid (8, 36), 256 threads, 2 tokens/thread, double-buffered tiles.
// ---------------------------------------------------------------------------
__global__ __launch_bounds__(256, 2) void scan_kernel(const float* __restrict__ x) {
    __shared__ int4 sQ[2][STC];
    __shared__ int  sB[2][STC];

    const int tid = threadIdx.x;
    const int tok0 = blockIdx.x * 512 + tid;
    const int tok1 = tok0 + 256;
    const int b = tok0 >> 10;
    const int grp = blockIdx.y;
    const int st0 = (grp * NST) / NGR;
    const int st1 = ((grp + 1) * NST) / NGR;

    const float maxX = __uint_as_float(g_scal[0]);
    const float maxC = __uint_as_float(g_scal[1]);
    const float sx = maxX * (1.0f / 127.0f);
    const float sc = maxC * (1.0f / 127.0f);
    const float s  = sx * sc;
    const float qx = 127.0f / maxX;

    const float* xp = x + (size_t)b * (DIM * 1024);
    int xq0[4], xq1[4];
#pragma unroll
    for (int w = 0; w < 4; w++) {
        int q0[4], q1[4];
#pragma unroll
        for (int j = 0; j < 4; j++) {
            int d = w * 4 + j;
            q0[j] = __float2int_rn(xp[d * 1024 + (tok0 & 1023)] * qx);
            q1[j] = __float2int_rn(xp[d * 1024 + (tok1 & 1023)] * qx);
        }
        xq0[w] = pack4(q0[0], q0[1], q0[2], q0[3]);
        xq1[w] = pack4(q1[0], q1[1], q1[2], q1[3]);
    }

    if (tid < STC)
        cpasync16(&sQ[0][tid], &g_Bq[st0 * STC + tid]);
    else if (tid < STC + 16)
        cpasync16(&sB[0][(tid - STC) * 4], &g_bias[st0 * STC + (tid - STC) * 4]);
    CP_COMMIT();

    for (int st = st0; st < st1; st++) {
        const int buf = (st - st0) & 1;
        if (st + 1 < st1) {
            if (tid < STC)
                cpasync16(&sQ[buf ^ 1][tid], &g_Bq[(st + 1) * STC + tid]);
            else if (tid < STC + 16)
                cpasync16(&sB[buf ^ 1][(tid - STC) * 4],
                          &g_bias[(st + 1) * STC + (tid - STC) * 4]);
            CP_COMMIT();
            CP_WAIT(1);
        } else {
            CP_WAIT(0);
        }
        __syncthreads();

        int m0 = INT_MIN, m1 = INT_MIN;
        const int4* q4 = sQ[buf];
        const int4* b4 = (const int4*)sB[buf];
#pragma unroll 4
        for (int g = 0; g < STC / 4; g++) {
            int4 bb = b4[g];
            int bias[4] = {bb.x, bb.y, bb.z, bb.w};
#pragma unroll
            for (int u = 0; u < 4; u++) {
                int4 q = q4[g * 4 + u];
                int a0 = __dp4a(q.x, xq0[0], bias[u]);
                a0 = __dp4a(q.y, xq0[1], a0);
                a0 = __dp4a(q.z, xq0[2], a0);
                a0 = __dp4a(q.w, xq0[3], a0);
                int a1 = __dp4a(q.x, xq1[0], bias[u]);
                a1 = __dp4a(q.y, xq1[1], a1);
                a1 = __dp4a(q.z, xq1[2], a1);
                a1 = __dp4a(q.w, xq1[3], a1);
                m0 = max(m0, a0);
                m1 = max(m1, a1);
            }
        }
        g_tb[(size_t)st * TOKENS + tok0] = (float)m0 * s;
        g_tb[(size_t)st * TOKENS + tok1] = (float)m1 * s;
        __syncthreads();
    }
}

// ---------------------------------------------------------------------------
// Phase 2: WARP-PER-TOKEN exact rescue. 4096 warps, warp-uniform candidate
// tiles in ascending order, coalesced codebook reads, warp argmax reduce.
// ---------------------------------------------------------------------------
__global__ __launch_bounds__(256) void finish_kernel(const float* __restrict__ x,
                                                     const float* __restrict__ cb,
                                                     float* __restrict__ out) {
    const int lane  = threadIdx.x & 31;
    const int token = blockIdx.x * 8 + (threadIdx.x >> 5);   // grid = 512
    const int bb = token >> 10, t = token & 1023;

    // every lane holds the full x vector (broadcast loads)
    float xr[DIM];
    float SAx = 0.0f;
#pragma unroll
    for (int d = 0; d < DIM; d++) {
        xr[d] = x[(size_t)bb * (DIM * 1024) + d * 1024 + t];
        SAx += fabsf(xr[d]);
    }

    // lane l owns tiles [32l, 32l+32): load maxima, local max
    float tb[32];
    float lmax = NINF;
#pragma unroll
    for (int j = 0; j < 32; j++) {
        tb[j] = g_tb[(size_t)(lane * 32 + j) * TOKENS + token];
        lmax = fmaxf(lmax, tb[j]);
    }
    float m = lmax;
#pragma unroll
    for (int off = 16; off > 0; off >>= 1)
        m = fmaxf(m, __shfl_xor_sync(0xffffffffu, m, off));

    const float maxX = __uint_as_float(g_scal[0]);
    const float maxC = __uint_as_float(g_scal[1]);
    const float SAc  = __uint_as_float(g_scal[2]);
    const float sx = maxX * (1.0f / 127.0f);
    const float sc = maxC * (1.0f / 127.0f);
    const float E = 0.5f * sc * SAx + 0.5f * sx * SAc
                  + 16.0f * sx * sc + sx * sc + 1e-2f;
    const float thr = m - 2.0f * E;

    // local candidate mask over this lane's 32 tiles
    unsigned cmask = 0u;
#pragma unroll
    for (int j = 0; j < 32; j++)
        if (tb[j] >= thr) cmask |= (1u << j);

    float best = NINF;
    int   bi   = 0x7fffffff;

    // iterate candidate tiles in ascending global order, warp-uniform
    for (int w = 0; w < 32; w++) {
        unsigned msk = __shfl_sync(0xffffffffu, cmask, w);
        while (msk) {
            int j = __ffs(msk) - 1;
            msk &= msk - 1;
            int ti = w * 32 + j;
            int c0 = ti * STC;
            // lane handles codes c0+lane and c0+32+lane (ascending per lane)
#pragma unroll
            for (int half = 0; half < 2; half++) {
                int c = c0 + half * 32 + lane;
                const float4* cr = (const float4*)(cb + (size_t)c * DIM);
                float acc = 0.0f, h = 0.0f;
#pragma unroll
                for (int v4 = 0; v4 < 4; v4++) {
                    float4 q = cr[v4];
                    acc = fmaf(q.x, xr[v4 * 4 + 0], acc);
                    h   = fmaf(q.x, q.x, h);
                    acc = fmaf(q.y, xr[v4 * 4 + 1], acc);
                    h   = fmaf(q.y, q.y, h);
                    acc = fmaf(q.z, xr[v4 * 4 + 2], acc);
                    h   = fmaf(q.z, q.z, h);
                    acc = fmaf(q.w, xr[v4 * 4 + 3], acc);
                    h   = fmaf(q.w, q.w, h);
                }
                float sscore = acc - 0.5f * h;
                // lane-local indices ascend -> strict > keeps first index
                if (sscore > best) { best = sscore; bi = c; }
            }
        }
    }

    // warp argmax reduce; ties -> smaller index (global first-index-wins)
#pragma unroll
    for (int off = 16; off > 0; off >>= 1) {
        float vb = __shfl_xor_sync(0xffffffffu, best, off);
        int   ib = __shfl_xor_sync(0xffffffffu, bi,   off);
        if (vb > best || (vb == best && ib < bi)) { best = vb; bi = ib; }
    }

    // gather + output + per-token error (lanes 0..15 = dims)
    float e = 0.0f;
    if (lane < DIM) {
        float qd = cb[(size_t)bi * DIM + lane];
        float df = qd - xr[lane];
        e = df * df;
        out[(size_t)bb * (DIM * 1024) + lane * 1024 + t] = qd;
    }
#pragma unroll
    for (int off = 16; off > 0; off >>= 1)
        e += __shfl_xor_sync(0xffffffffu, e, off);
    if (lane == 0) g_err[token] = e;
}

// ---------------------------------------------------------------------------
// Phase 3: deterministic loss reduction.
// ---------------------------------------------------------------------------
__global__ __launch_bounds__(1024) void loss_kernel(float* __restrict__ out,
                                                    int out_size) {
    __shared__ float sh[1024];
    int tid = threadIdx.x;
    float v = 0.0f;
#pragma unroll
    for (int i = 0; i < TOKENS / 1024; i++)
        v += g_err[tid * (TOKENS / 1024) + i];
    sh[tid] = v;
    __syncthreads();
    for (int stride = 512; stride > 0; stride >>= 1) {
        if (tid < stride) sh[tid] += sh[tid + stride];
        __syncthreads();
    }
    if (tid == 0 && out_size > NCODES)
        out[NCODES] = sh[0] / (float)(TOKENS * DIM);
}

// ---------------------------------------------------------------------------
extern "C" void kernel_launch(void* const* d_in, const int* in_sizes, int n_in,
                              void* d_out, int out_size) {
    const float* x  = (const float*)d_in[0];   // [4,16,1024]
    const float* cb = (const float*)d_in[1];   // [65536,16]
    float* out = (float*)d_out;

    init_kernel<<<1, 32>>>();
    prepA_kernel<<<NCODES / 256, 256>>>(x, cb);
    prepB_kernel<<<NCODES / 256, 256>>>(cb);

    dim3 grid(TOKENS / 512, NGR);
    scan_kernel<<<grid, 256>>>(x);

    finish_kernel<<<TOKENS / 8, 256>>>(x, cb, out);

    loss_kernel<<<1, 1024>>>(out, out_size);
}

// round 7
// speedup vs baseline: 41.3715x; 1.1492x over previous
#include <cuda_runtime.h>
#include <math.h>
#include <stdint.h>

// ---------------------------------------------------------------------------
// Quantizer: x [4,16,1024] f32, codebook [65536,16] f32.
// out[0:65536] = nearest codebook entry per token, [B,D,T]; out[65536] = loss.
//
// Pass 1: int8 dp4a scores (exact int arithmetic, rigorous error bound E),
// per-(token, 64-code tile) max, stored TRANSPOSED [token][tile].
// Pass 2 (warp-per-token): exact fp32 rescore of tiles within 2E of the max
// -> exact argmin (index tie-break -> first index wins, order-independent).
// ---------------------------------------------------------------------------

#define TOKENS   4096
#define NCODES   65536
#define DIM      16
#define STC      64                  // codes per tile
#define NST      (NCODES / STC)      // 1024 tiles
#define TPC      4                   // tiles per scan CTA
#define NGR      (NST / TPC)         // 256 code groups (grid.y)
#define NINF     __int_as_float(0xff800000)
#define FULL     0xffffffffu

__device__ unsigned g_scal[4];            // maxX, maxC, SAc (float bits)
__device__ int4     g_Bq[NCODES];         // packed int8 codes, 1 MB
__device__ int      g_bias[NCODES];       // bias in int score units
__device__ float    g_tbT[(size_t)TOKENS * NST]; // [token][tile] maxima, 16 MB
__device__ float    g_err[TOKENS];

__device__ __forceinline__ void cpasync16(const void* dst_smem, const void* src) {
    unsigned s = (unsigned)__cvta_generic_to_shared(dst_smem);
    asm volatile("cp.async.cg.shared.global [%0], [%1], 16;" :: "r"(s), "l"(src));
}
#define CP_COMMIT() asm volatile("cp.async.commit_group;")
#define CP_WAIT0()  asm volatile("cp.async.wait_group 0;")

__device__ __forceinline__ int pack4(int a0, int a1, int a2, int a3) {
    return (a0 & 0xFF) | ((a1 & 0xFF) << 8) | ((a2 & 0xFF) << 16) | (a3 << 24);
}

// ---------------------------------------------------------------------------
__global__ void init_kernel() {
    if (threadIdx.x < 4) g_scal[threadIdx.x] = 0u;
}

// Phase 0a: maxima reductions (deterministic: bitwise atomicMax on positive
// float patterns is order-independent). float4-coalesced codebook reads.
__global__ __launch_bounds__(256) void prepA_kernel(const float* __restrict__ x,
                                                    const float* __restrict__ cb) {
    __shared__ float sm[3][256];
    int i = blockIdx.x * 256 + threadIdx.x;          // 0..65535
    float ax = fabsf(x[i]);                          // x has exactly 65536 elems
    const float4* c4 = (const float4*)(cb + (size_t)i * DIM);
    float mc = 0.0f, sa = 0.0f;
#pragma unroll
    for (int v = 0; v < 4; v++) {
        float4 q = c4[v];
        float a0 = fabsf(q.x), a1 = fabsf(q.y), a2 = fabsf(q.z), a3 = fabsf(q.w);
        mc = fmaxf(fmaxf(mc, fmaxf(a0, a1)), fmaxf(a2, a3));
        sa += a0; sa += a1; sa += a2; sa += a3;
    }
    sm[0][threadIdx.x] = ax; sm[1][threadIdx.x] = mc; sm[2][threadIdx.x] = sa;
    __syncthreads();
    for (int s = 128; s > 0; s >>= 1) {
        if (threadIdx.x < s) {
#pragma unroll
            for (int k = 0; k < 3; k++)
                sm[k][threadIdx.x] = fmaxf(sm[k][threadIdx.x], sm[k][threadIdx.x + s]);
        }
        __syncthreads();
    }
    if (threadIdx.x == 0) {
#pragma unroll
        for (int k = 0; k < 3; k++)
            atomicMax(&g_scal[k], __float_as_uint(sm[k][0]));
    }
}

// Phase 0b: quantize codebook to int8 + int bias (float4 reads).
__global__ __launch_bounds__(256) void prepB_kernel(const float* __restrict__ cb) {
    int i = blockIdx.x * 256 + threadIdx.x;
    const float maxX = __uint_as_float(g_scal[0]);
    const float maxC = __uint_as_float(g_scal[1]);
    const float sx = maxX * (1.0f / 127.0f);
    const float sc = maxC * (1.0f / 127.0f);
    const float qc = 127.0f / maxC;
    const float4* c4 = (const float4*)(cb + (size_t)i * DIM);
    int q[DIM];
    float h = 0.0f;
#pragma unroll
    for (int v = 0; v < 4; v++) {
        float4 p = c4[v];
        h = fmaf(p.x, p.x, h); q[v * 4 + 0] = __float2int_rn(p.x * qc);
        h = fmaf(p.y, p.y, h); q[v * 4 + 1] = __float2int_rn(p.y * qc);
        h = fmaf(p.z, p.z, h); q[v * 4 + 2] = __float2int_rn(p.z * qc);
        h = fmaf(p.w, p.w, h); q[v * 4 + 3] = __float2int_rn(p.w * qc);
    }
    int4 w;
    w.x = pack4(q[0], q[1], q[2], q[3]);
    w.y = pack4(q[4], q[5], q[6], q[7]);
    w.z = pack4(q[8], q[9], q[10], q[11]);
    w.w = pack4(q[12], q[13], q[14], q[15]);
    g_Bq[i] = w;
    g_bias[i] = __float2int_rn(-0.5f * h / (sx * sc));
}

// ---------------------------------------------------------------------------
// Phase 1: int8 dp4a scan. grid (4 batches, 256 groups), 256 threads,
// 4 tokens/thread, 4 tiles (256 codes, 5KB) per CTA. 4 CTAs/SM.
// ---------------------------------------------------------------------------
__global__ __launch_bounds__(256, 4) void scan_kernel(const float* __restrict__ x) {
    __shared__ int4 sQ[TPC * STC];     // 4 KB (256 code rows)
    __shared__ int  sB[TPC * STC];     // 1 KB

    const int tid = threadIdx.x;
    const int batch = blockIdx.x;              // 0..3
    const int grp = blockIdx.y;                // 0..255
    const int c0 = grp * (TPC * STC);

    // async-load this CTA's 256 code rows + biases
    cpasync16(&sQ[tid], &g_Bq[c0 + tid]);
    if (tid < 64) cpasync16(&sB[tid * 4], &g_bias[c0 + tid * 4]);
    CP_COMMIT();

    const float maxX = __uint_as_float(g_scal[0]);
    const float maxC = __uint_as_float(g_scal[1]);
    const float sx = maxX * (1.0f / 127.0f);
    const float sc = maxC * (1.0f / 127.0f);
    const float s  = sx * sc;
    const float qx = 127.0f / maxX;

    // quantize 4 tokens (tid, tid+256, tid+512, tid+768 within batch)
    const float* xp = x + (size_t)batch * (DIM * 1024);
    int xq[4][4];
#pragma unroll
    for (int tk = 0; tk < 4; tk++) {
        int t = tk * 256 + tid;
#pragma unroll
        for (int w = 0; w < 4; w++) {
            int q0 = __float2int_rn(xp[(w * 4 + 0) * 1024 + t] * qx);
            int q1 = __float2int_rn(xp[(w * 4 + 1) * 1024 + t] * qx);
            int q2 = __float2int_rn(xp[(w * 4 + 2) * 1024 + t] * qx);
            int q3 = __float2int_rn(xp[(w * 4 + 3) * 1024 + t] * qx);
            xq[tk][w] = pack4(q0, q1, q2, q3);
        }
    }

    CP_WAIT0();
    __syncthreads();

    float4 fb[4];                       // [token] -> 4 tile maxima
    const int4* b4 = (const int4*)sB;

#pragma unroll
    for (int st = 0; st < TPC; st++) {
        int m[4];
#pragma unroll
        for (int tk = 0; tk < 4; tk++) m[tk] = INT_MIN;
#pragma unroll 4
        for (int g = 0; g < STC / 4; g++) {
            int4 bb = b4[st * (STC / 4) + g];
            int bias[4] = {bb.x, bb.y, bb.z, bb.w};
#pragma unroll
            for (int u = 0; u < 4; u++) {
                int4 q = sQ[st * STC + g * 4 + u];
#pragma unroll
                for (int tk = 0; tk < 4; tk++) {
                    int a = __dp4a(q.x, xq[tk][0], bias[u]);
                    a = __dp4a(q.y, xq[tk][1], a);
                    a = __dp4a(q.z, xq[tk][2], a);
                    a = __dp4a(q.w, xq[tk][3], a);
                    m[tk] = max(m[tk], a);
                }
            }
        }
        float f0 = (float)m[0] * s, f1 = (float)m[1] * s;
        float f2 = (float)m[2] * s, f3 = (float)m[3] * s;
        if (st == 0) { fb[0].x = f0; fb[1].x = f1; fb[2].x = f2; fb[3].x = f3; }
        if (st == 1) { fb[0].y = f0; fb[1].y = f1; fb[2].y = f2; fb[3].y = f3; }
        if (st == 2) { fb[0].z = f0; fb[1].z = f1; fb[2].z = f2; fb[3].z = f3; }
        if (st == 3) { fb[0].w = f0; fb[1].w = f1; fb[2].w = f2; fb[3].w = f3; }
    }

    // transposed store: 16B per token, [token][tile]
#pragma unroll
    for (int tk = 0; tk < 4; tk++) {
        int token = batch * 1024 + tk * 256 + tid;
        *(float4*)&g_tbT[(size_t)token * NST + grp * TPC] = fb[tk];
    }
}

// ---------------------------------------------------------------------------
// Phase 2: warp-per-token exact rescue; coalesced tb reads; candidate
// iteration order-free (index tie-break in the compare).
// ---------------------------------------------------------------------------
__global__ __launch_bounds__(256) void finish_kernel(const float* __restrict__ x,
                                                     const float* __restrict__ cb,
                                                     float* __restrict__ out) {
    const int lane  = threadIdx.x & 31;
    const int token = blockIdx.x * 8 + (threadIdx.x >> 5);   // grid = 512
    const int bb = token >> 10, t = token & 1023;

    float xr[DIM];
    float SAx = 0.0f;
#pragma unroll
    for (int d = 0; d < DIM; d++) {
        xr[d] = x[(size_t)bb * (DIM * 1024) + d * 1024 + t];
        SAx += fabsf(xr[d]);
    }

    // coalesced: load 1024 tile maxima; lane covers tiles j*128 + lane*4 + e
    const float* tbp = g_tbT + (size_t)token * NST;
    float4 tv[8];
    float lmax = NINF;
#pragma unroll
    for (int j = 0; j < 8; j++) {
        tv[j] = *(const float4*)&tbp[j * 128 + lane * 4];
        lmax = fmaxf(lmax, fmaxf(fmaxf(tv[j].x, tv[j].y), fmaxf(tv[j].z, tv[j].w)));
    }
    float m = lmax;
#pragma unroll
    for (int off = 16; off > 0; off >>= 1)
        m = fmaxf(m, __shfl_xor_sync(FULL, m, off));

    const float maxX = __uint_as_float(g_scal[0]);
    const float maxC = __uint_as_float(g_scal[1]);
    const float SAc  = __uint_as_float(g_scal[2]);
    const float sx = maxX * (1.0f / 127.0f);
    const float sc = maxC * (1.0f / 127.0f);
    const float E = 0.5f * sc * SAx + 0.5f * sx * SAc
                  + 16.0f * sx * sc + sx * sc + 1e-2f;
    const float thr = m - 2.0f * E;

    // candidate mask: bit (j*4+e) -> tile j*128 + lane*4 + e
    unsigned cmask = 0u;
#pragma unroll
    for (int j = 0; j < 8; j++) {
        if (tv[j].x >= thr) cmask |= 1u << (j * 4 + 0);
        if (tv[j].y >= thr) cmask |= 1u << (j * 4 + 1);
        if (tv[j].z >= thr) cmask |= 1u << (j * 4 + 2);
        if (tv[j].w >= thr) cmask |= 1u << (j * 4 + 3);
    }

    float best = NINF;
    int   bi   = 0x7fffffff;

    unsigned act = __ballot_sync(FULL, cmask != 0u);
    while (act) {
        int w = __ffs(act) - 1;
        act &= act - 1;
        unsigned msk = __shfl_sync(FULL, cmask, w);
        while (msk) {
            int bpos = __ffs(msk) - 1;
            msk &= msk - 1;
            int ti = (bpos >> 2) * 128 + w * 4 + (bpos & 3);
            int cbase = ti * STC;
#pragma unroll
            for (int half = 0; half < 2; half++) {
                int c = cbase + half * 32 + lane;
                const float4* cr = (const float4*)(cb + (size_t)c * DIM);
                float acc = 0.0f, h = 0.0f;
#pragma unroll
                for (int v4 = 0; v4 < 4; v4++) {
                    float4 q = cr[v4];
                    acc = fmaf(q.x, xr[v4 * 4 + 0], acc); h = fmaf(q.x, q.x, h);
                    acc = fmaf(q.y, xr[v4 * 4 + 1], acc); h = fmaf(q.y, q.y, h);
                    acc = fmaf(q.z, xr[v4 * 4 + 2], acc); h = fmaf(q.z, q.z, h);
                    acc = fmaf(q.w, xr[v4 * 4 + 3], acc); h = fmaf(q.w, q.w, h);
                }
                float sscore = acc - 0.5f * h;
                // order-free first-index-wins
                if (sscore > best || (sscore == best && c < bi)) {
                    best = sscore; bi = c;
                }
            }
        }
    }

    // warp argmax reduce; ties -> smaller index
#pragma unroll
    for (int off = 16; off > 0; off >>= 1) {
        float vb = __shfl_xor_sync(FULL, best, off);
        int   ib = __shfl_xor_sync(FULL, bi,   off);
        if (vb > best || (vb == best && ib < bi)) { best = vb; bi = ib; }
    }

    float e = 0.0f;
    if (lane < DIM) {
        float qd = cb[(size_t)bi * DIM + lane];
        float df = qd - xr[lane];
        e = df * df;
        out[(size_t)bb * (DIM * 1024) + lane * 1024 + t] = qd;
    }
#pragma unroll
    for (int off = 16; off > 0; off >>= 1)
        e += __shfl_xor_sync(FULL, e, off);
    if (lane == 0) g_err[token] = e;
}

// ---------------------------------------------------------------------------
// Phase 3: deterministic loss reduction.
// ---------------------------------------------------------------------------
__global__ __launch_bounds__(1024) void loss_kernel(float* __restrict__ out,
                                                    int out_size) {
    __shared__ float sh[1024];
    int tid = threadIdx.x;
    float v = 0.0f;
#pragma unroll
    for (int i = 0; i < TOKENS / 1024; i++)
        v += g_err[tid * (TOKENS / 1024) + i];
    sh[tid] = v;
    __syncthreads();
    for (int stride = 512; stride > 0; stride >>= 1) {
        if (tid < stride) sh[tid] += sh[tid + stride];
        __syncthreads();
    }
    if (tid == 0 && out_size > NCODES)
        out[NCODES] = sh[0] / (float)(TOKENS * DIM);
}

// ---------------------------------------------------------------------------
extern "C" void kernel_launch(void* const* d_in, const int* in_sizes, int n_in,
                              void* d_out, int out_size) {
    const float* x  = (const float*)d_in[0];   // [4,16,1024]
    const float* cb = (const float*)d_in[1];   // [65536,16]
    float* out = (float*)d_out;

    init_kernel<<<1, 32>>>();
    prepA_kernel<<<NCODES / 256, 256>>>(x, cb);
    prepB_kernel<<<NCODES / 256, 256>>>(cb);

    dim3 grid(4, NGR);
    scan_kernel<<<grid, 256>>>(x);

    finish_kernel<<<TOKENS / 8, 256>>>(x, cb, out);

    loss_kernel<<<1, 1024>>>(out, out_size);
}

// round 9
// speedup vs baseline: 41.5373x; 1.0040x over previous
#include <cuda_runtime.h>
#include <math.h>
#include <stdint.h>

// ---------------------------------------------------------------------------
// Quantizer: x [4,16,1024] f32, codebook [65536,16] f32.
// out[0:65536] = nearest codebook entry per token, [B,D,T]; out[65536] = loss.
//
// 4 launches:
//   prepA : per-block |.| maxima partials (no atomics)
//   prepB : reduce partials -> scales; quantize codebook to int8 + int bias;
//           zero the loss accumulator/ticket
//   scan  : int8 dp4a scores, per-(token, 64-code tile) max, transposed store
//   finish: warp-per-token exact fp32 rescue within rigorous bound 2E,
//           fused deterministic fixed-point loss reduction
// ---------------------------------------------------------------------------

#define TOKENS   4096
#define NCODES   65536
#define DIM      16
#define STC      64                  // codes per tile
#define NST      (NCODES / STC)      // 1024 tiles
#define TPC      4                   // tiles per scan CTA
#define NGR      (NST / TPC)         // 256 code groups
#define PBLK     256                 // prepA blocks
#define FGRID    (TOKENS / 8)        // finish grid (8 warps/CTA)
#define NINF     __int_as_float(0xff800000)
#define FULL     0xffffffffu
#define LSCALE   4294967296.0        // 2^32 fixed-point loss scale

__device__ float    g_part[PBLK * 4];     // per-block partial maxima
__device__ unsigned g_scal[4];            // maxX, maxC, SAc (float bits)
__device__ int4     g_Bq[NCODES];         // packed int8 codes, 1 MB
__device__ int      g_bias[NCODES];       // bias in int score units
__device__ float    g_tbT[(size_t)TOKENS * NST]; // [token][tile] maxima, 16 MB
__device__ unsigned long long g_lsum;     // fixed-point loss accumulator
__device__ unsigned g_cnt;                // completion ticket

__device__ __forceinline__ void cpasync16(const void* dst_smem, const void* src) {
    unsigned s = (unsigned)__cvta_generic_to_shared(dst_smem);
    asm volatile("cp.async.cg.shared.global [%0], [%1], 16;" :: "r"(s), "l"(src));
}
#define CP_COMMIT() asm volatile("cp.async.commit_group;")
#define CP_WAIT0()  asm volatile("cp.async.wait_group 0;")

__device__ __forceinline__ int pack4(int a0, int a1, int a2, int a3) {
    return (a0 & 0xFF) | ((a1 & 0xFF) << 8) | ((a2 & 0xFF) << 16) | (a3 << 24);
}

// ---------------------------------------------------------------------------
// prepA: per-block maxima of |x|, |c|, Sum|c| -> g_part (no atomics, no init).
// ---------------------------------------------------------------------------
__global__ __launch_bounds__(256) void prepA_kernel(const float* __restrict__ x,
                                                    const float* __restrict__ cb) {
    __shared__ float sm[3][256];
    int i = blockIdx.x * 256 + threadIdx.x;          // 0..65535
    float ax = fabsf(x[i]);                          // x has exactly 65536 elems
    const float4* c4 = (const float4*)(cb + (size_t)i * DIM);
    float mc = 0.0f, sa = 0.0f;
#pragma unroll
    for (int v = 0; v < 4; v++) {
        float4 q = c4[v];
        float a0 = fabsf(q.x), a1 = fabsf(q.y), a2 = fabsf(q.z), a3 = fabsf(q.w);
        mc = fmaxf(fmaxf(mc, fmaxf(a0, a1)), fmaxf(a2, a3));
        sa += a0; sa += a1; sa += a2; sa += a3;
    }
    sm[0][threadIdx.x] = ax; sm[1][threadIdx.x] = mc; sm[2][threadIdx.x] = sa;
    __syncthreads();
    for (int s = 128; s > 0; s >>= 1) {
        if (threadIdx.x < s) {
#pragma unroll
            for (int k = 0; k < 3; k++)
                sm[k][threadIdx.x] = fmaxf(sm[k][threadIdx.x], sm[k][threadIdx.x + s]);
        }
        __syncthreads();
    }
    if (threadIdx.x < 3) g_part[blockIdx.x * 4 + threadIdx.x] = sm[threadIdx.x][0];
}

// ---------------------------------------------------------------------------
// prepB: reduce partials (each block, redundant, L2-hot), publish g_scal,
// quantize codebook, zero loss accumulator.
// ---------------------------------------------------------------------------
__global__ __launch_bounds__(256) void prepB_kernel(const float* __restrict__ cb) {
    __shared__ float sm[3][256];
    const int tid = threadIdx.x;
    sm[0][tid] = g_part[tid * 4 + 0];
    sm[1][tid] = g_part[tid * 4 + 1];
    sm[2][tid] = g_part[tid * 4 + 2];
    __syncthreads();
    for (int s = 128; s > 0; s >>= 1) {
        if (tid < s) {
#pragma unroll
            for (int k = 0; k < 3; k++)
                sm[k][tid] = fmaxf(sm[k][tid], sm[k][tid + s]);
        }
        __syncthreads();
    }
    const float maxX = sm[0][0], maxC = sm[1][0], SAc = sm[2][0];
    if (blockIdx.x == 0 && tid == 0) {
        g_scal[0] = __float_as_uint(maxX);
        g_scal[1] = __float_as_uint(maxC);
        g_scal[2] = __float_as_uint(SAc);
        g_lsum = 0ull;                 // re-zeroed every replay before finish
        g_cnt  = 0u;
    }

    int i = blockIdx.x * 256 + tid;
    const float sx = maxX * (1.0f / 127.0f);
    const float sc = maxC * (1.0f / 127.0f);
    const float qc = 127.0f / maxC;
    const float4* c4 = (const float4*)(cb + (size_t)i * DIM);
    int q[DIM];
    float h = 0.0f;
#pragma unroll
    for (int v = 0; v < 4; v++) {
        float4 p = c4[v];
        h = fmaf(p.x, p.x, h); q[v * 4 + 0] = __float2int_rn(p.x * qc);
        h = fmaf(p.y, p.y, h); q[v * 4 + 1] = __float2int_rn(p.y * qc);
        h = fmaf(p.z, p.z, h); q[v * 4 + 2] = __float2int_rn(p.z * qc);
        h = fmaf(p.w, p.w, h); q[v * 4 + 3] = __float2int_rn(p.w * qc);
    }
    int4 w;
    w.x = pack4(q[0], q[1], q[2], q[3]);
    w.y = pack4(q[4], q[5], q[6], q[7]);
    w.z = pack4(q[8], q[9], q[10], q[11]);
    w.w = pack4(q[12], q[13], q[14], q[15]);
    g_Bq[i] = w;
    g_bias[i] = __float2int_rn(-0.5f * h / (sx * sc));
}

// ---------------------------------------------------------------------------
// scan: int8 dp4a. grid (4 batches, 256 groups), 256 thr, 4 tokens/thread,
// 4 tiles (256 codes, 5 KB smem) per CTA, 4 CTAs/SM. ~84% of dp4a pipe.
// ---------------------------------------------------------------------------
__global__ __launch_bounds__(256, 4) void scan_kernel(const float* __restrict__ x) {
    __shared__ int4 sQ[TPC * STC];     // 4 KB
    __shared__ int  sB[TPC * STC];     // 1 KB

    const int tid = threadIdx.x;
    const int batch = blockIdx.x;              // 0..3
    const int grp = blockIdx.y;                // 0..255
    const int c0 = grp * (TPC * STC);

    cpasync16(&sQ[tid], &g_Bq[c0 + tid]);
    if (tid < 64) cpasync16(&sB[tid * 4], &g_bias[c0 + tid * 4]);
    CP_COMMIT();

    const float maxX = __uint_as_float(g_scal[0]);
    const float maxC = __uint_as_float(g_scal[1]);
    const float sx = maxX * (1.0f / 127.0f);
    const float sc = maxC * (1.0f / 127.0f);
    const float s  = sx * sc;
    const float qx = 127.0f / maxX;

    const float* xp = x + (size_t)batch * (DIM * 1024);
    int xq[4][4];
#pragma unroll
    for (int tk = 0; tk < 4; tk++) {
        int t = tk * 256 + tid;
#pragma unroll
        for (int w = 0; w < 4; w++) {
            int q0 = __float2int_rn(xp[(w * 4 + 0) * 1024 + t] * qx);
            int q1 = __float2int_rn(xp[(w * 4 + 1) * 1024 + t] * qx);
            int q2 = __float2int_rn(xp[(w * 4 + 2) * 1024 + t] * qx);
            int q3 = __float2int_rn(xp[(w * 4 + 3) * 1024 + t] * qx);
            xq[tk][w] = pack4(q0, q1, q2, q3);
        }
    }

    CP_WAIT0();
    __syncthreads();

    float4 fb[4];
    const int4* b4 = (const int4*)sB;

#pragma unroll
    for (int st = 0; st < TPC; st++) {
        int m[4];
#pragma unroll
        for (int tk = 0; tk < 4; tk++) m[tk] = INT_MIN;
#pragma unroll 4
        for (int g = 0; g < STC / 4; g++) {
            int4 bb = b4[st * (STC / 4) + g];
            int bias[4] = {bb.x, bb.y, bb.z, bb.w};
#pragma unroll
            for (int u = 0; u < 4; u++) {
                int4 q = sQ[st * STC + g * 4 + u];
#pragma unroll
                for (int tk = 0; tk < 4; tk++) {
                    int a = __dp4a(q.x, xq[tk][0], bias[u]);
                    a = __dp4a(q.y, xq[tk][1], a);
                    a = __dp4a(q.z, xq[tk][2], a);
                    a = __dp4a(q.w, xq[tk][3], a);
                    m[tk] = max(m[tk], a);
                }
            }
        }
        float f0 = (float)m[0] * s, f1 = (float)m[1] * s;
        float f2 = (float)m[2] * s, f3 = (float)m[3] * s;
        if (st == 0) { fb[0].x = f0; fb[1].x = f1; fb[2].x = f2; fb[3].x = f3; }
        if (st == 1) { fb[0].y = f0; fb[1].y = f1; fb[2].y = f2; fb[3].y = f3; }
        if (st == 2) { fb[0].z = f0; fb[1].z = f1; fb[2].z = f2; fb[3].z = f3; }
        if (st == 3) { fb[0].w = f0; fb[1].w = f1; fb[2].w = f2; fb[3].w = f3; }
    }

#pragma unroll
    for (int tk = 0; tk < 4; tk++) {
        int token = batch * 1024 + tk * 256 + tid;
        *(float4*)&g_tbT[(size_t)token * NST + grp * TPC] = fb[tk];
    }
}

// ---------------------------------------------------------------------------
// finish: warp-per-token exact rescue + fused deterministic loss.
// ---------------------------------------------------------------------------
__global__ __launch_bounds__(256) void finish_kernel(const float* __restrict__ x,
                                                     const float* __restrict__ cb,
                                                     float* __restrict__ out,
                                                     int out_size) {
    __shared__ float sh_err[8];
    const int lane  = threadIdx.x & 31;
    const int warp  = threadIdx.x >> 5;
    const int token = blockIdx.x * 8 + warp;
    const int bb = token >> 10, t = token & 1023;

    float xr[DIM];
    float SAx = 0.0f;
#pragma unroll
    for (int d = 0; d < DIM; d++) {
        xr[d] = x[(size_t)bb * (DIM * 1024) + d * 1024 + t];
        SAx += fabsf(xr[d]);
    }

    const float* tbp = g_tbT + (size_t)token * NST;
    float4 tv[8];
    float lmax = NINF;
#pragma unroll
    for (int j = 0; j < 8; j++) {
        tv[j] = *(const float4*)&tbp[j * 128 + lane * 4];
        lmax = fmaxf(lmax, fmaxf(fmaxf(tv[j].x, tv[j].y), fmaxf(tv[j].z, tv[j].w)));
    }
    float m = lmax;
#pragma unroll
    for (int off = 16; off > 0; off >>= 1)
        m = fmaxf(m, __shfl_xor_sync(FULL, m, off));

    const float maxX = __uint_as_float(g_scal[0]);
    const float maxC = __uint_as_float(g_scal[1]);
    const float SAc  = __uint_as_float(g_scal[2]);
    const float sx = maxX * (1.0f / 127.0f);
    const float sc = maxC * (1.0f / 127.0f);
    const float E = 0.5f * sc * SAx + 0.5f * sx * SAc
                  + 16.0f * sx * sc + sx * sc + 1e-2f;
    const float thr = m - 2.0f * E;

    unsigned cmask = 0u;
#pragma unroll
    for (int j = 0; j < 8; j++) {
        if (tv[j].x >= thr) cmask |= 1u << (j * 4 + 0);
        if (tv[j].y >= thr) cmask |= 1u << (j * 4 + 1);
        if (tv[j].z >= thr) cmask |= 1u << (j * 4 + 2);
        if (tv[j].w >= thr) cmask |= 1u << (j * 4 + 3);
    }

    float best = NINF;
    int   bi   = 0x7fffffff;

    unsigned act = __ballot_sync(FULL, cmask != 0u);
    while (act) {
        int w = __ffs(act) - 1;
        act &= act - 1;
        unsigned msk = __shfl_sync(FULL, cmask, w);
        while (msk) {
            int bpos = __ffs(msk) - 1;
            msk &= msk - 1;
            int ti = (bpos >> 2) * 128 + w * 4 + (bpos & 3);
            int cbase = ti * STC;
#pragma unroll
            for (int half = 0; half < 2; half++) {
                int c = cbase + half * 32 + lane;
                const float4* cr = (const float4*)(cb + (size_t)c * DIM);
                float acc = 0.0f, h = 0.0f;
#pragma unroll
                for (int v4 = 0; v4 < 4; v4++) {
                    float4 q = cr[v4];
                    acc = fmaf(q.x, xr[v4 * 4 + 0], acc); h = fmaf(q.x, q.x, h);
                    acc = fmaf(q.y, xr[v4 * 4 + 1], acc); h = fmaf(q.y, q.y, h);
                    acc = fmaf(q.z, xr[v4 * 4 + 2], acc); h = fmaf(q.z, q.z, h);
                    acc = fmaf(q.w, xr[v4 * 4 + 3], acc); h = fmaf(q.w, q.w, h);
                }
                float sscore = acc - 0.5f * h;
                if (sscore > best || (sscore == best && c < bi)) {
                    best = sscore; bi = c;       // order-free first-index-wins
                }
            }
        }
    }

#pragma unroll
    for (int off = 16; off > 0; off >>= 1) {
        float vb = __shfl_xor_sync(FULL, best, off);
        int   ib = __shfl_xor_sync(FULL, bi,   off);
        if (vb > best || (vb == best && ib < bi)) { best = vb; bi = ib; }
    }

    float e = 0.0f;
    if (lane < DIM) {
        float qd = cb[(size_t)bi * DIM + lane];
        float df = qd - xr[lane];
        e = df * df;
        out[(size_t)bb * (DIM * 1024) + lane * 1024 + t] = qd;
    }
#pragma unroll
    for (int off = 16; off > 0; off >>= 1)
        e += __shfl_xor_sync(FULL, e, off);
    if (lane == 0) sh_err[warp] = e;

    // fused deterministic loss: fixed-point atomic sum + last-CTA ticket
    __syncthreads();
    if (threadIdx.x == 0) {
        float ce = 0.0f;
#pragma unroll
        for (int w = 0; w < 8; w++) ce += sh_err[w];    // fixed order
        unsigned long long r =
            (unsigned long long)__double2ll_rn((double)ce * LSCALE);
        atomicAdd(&g_lsum, r);
        __threadfence();
        unsigned ticket = atomicAdd(&g_cnt, 1u);
        if (ticket == FGRID - 1 && out_size > NCODES) {
            double sum = (double)*(volatile unsigned long long*)&g_lsum;
            out[NCODES] = (float)(sum / LSCALE / (double)(TOKENS * DIM));
        }
    }
}

// ---------------------------------------------------------------------------
extern "C" void kernel_launch(void* const* d_in, const int* in_sizes, int n_in,
                              void* d_out, int out_size) {
    const float* x  = (const float*)d_in[0];   // [4,16,1024]
    const float* cb = (const float*)d_in[1];   // [65536,16]
    float* out = (float*)d_out;

    prepA_kernel<<<PBLK, 256>>>(x, cb);
    prepB_kernel<<<NCODES / 256, 256>>>(cb);

    dim3 grid(4, NGR);
    scan_kernel<<<grid, 256>>>(x);

    finish_kernel<<<FGRID, 256>>>(x, cb, out, out_size);
}